// round 1
// baseline (speedup 1.0000x reference)
#include <cuda_runtime.h>
#include <math.h>
#include <stdint.h>

#define BATCH 8
#define DIMC 512
#define HW 1024
#define HEADS 8
#define HD 64
#define LCTX 77
#define CTXD 768
#define TKV 1101      // 77 ctx + 1024 image keys
#define NCHUNK 18     // ceil(1101/64)

// ---- scratch (device globals; no allocation allowed) ----
__device__ float g_xn[BATCH * DIMC * HW];        // 16 MB groupnormed x
__device__ float g_qkv[BATCH * 3 * DIMC * HW];   // 50 MB qkv projections
__device__ float g_ckv[BATCH * 2 * DIMC * LCTX]; // 2.5 MB context kv, [b][o][l]
__device__ float g_attn[BATCH * DIMC * HW];      // 16 MB attention output

// ============================================================
// GroupNorm: one block per (b, group). 16 ch * 1024 spatial = 16384 contiguous.
// ============================================================
__global__ void gn_kernel(const float* __restrict__ x, const float* __restrict__ gamma,
                          const float* __restrict__ beta, float* __restrict__ xn) {
    __shared__ float ssum[256], ssq[256];
    int bg = blockIdx.x;
    int b = bg >> 5, g = bg & 31;
    const float* xp = x + ((size_t)b * DIMC + g * 16) * HW;
    float* xo = xn + ((size_t)b * DIMC + g * 16) * HW;
    int tid = threadIdx.x;

    float s = 0.f, sq = 0.f;
#pragma unroll
    for (int i = 0; i < 64; i++) {
        float v = xp[tid + i * 256];
        s += v; sq += v * v;
    }
    ssum[tid] = s; ssq[tid] = sq;
    __syncthreads();
    for (int off = 128; off > 0; off >>= 1) {
        if (tid < off) { ssum[tid] += ssum[tid + off]; ssq[tid] += ssq[tid + off]; }
        __syncthreads();
    }
    float mu = ssum[0] * (1.f / 16384.f);
    float var = ssq[0] * (1.f / 16384.f) - mu * mu;
    float inv = rsqrtf(var + 1e-5f);
#pragma unroll
    for (int i = 0; i < 64; i++) {
        int idx = tid + i * 256;
        int c = g * 16 + (idx >> 10);
        xo[idx] = (xp[idx] - mu) * inv * gamma[c] + beta[c];
    }
}

// ============================================================
// SGEMM: C[b][m][n] = sum_k W[m][k] * X[b][k][n] + bias[m] (+ res[b][m][n])
// 128x128 tile, BK=8, 256 threads, 8x8 microtile.
// ============================================================
__global__ void gemm128(const float* __restrict__ W, const float* __restrict__ bias,
                        const float* __restrict__ X, const float* __restrict__ res,
                        float* __restrict__ C, int M, int N, int K) {
    __shared__ float ws[8 * 128];
    __shared__ float xs[8 * 128];
    int b = blockIdx.z;
    int m0 = blockIdx.y * 128, n0 = blockIdx.x * 128;
    const float* Xb = X + (size_t)b * K * N;
    int tid = threadIdx.x;
    int tx = tid & 15, ty = tid >> 4;

    float acc[8][8];
#pragma unroll
    for (int i = 0; i < 8; i++)
#pragma unroll
        for (int j = 0; j < 8; j++) acc[i][j] = 0.f;

    int wm = tid >> 1;            // 0..127
    int wk = (tid & 1) * 4;       // 0 or 4
    int xn4 = (tid & 31) * 4;     // 0..124
    int xk = tid >> 5;            // 0..7

    for (int k0 = 0; k0 < K; k0 += 8) {
        float4 wv = *(const float4*)(W + (size_t)(m0 + wm) * K + k0 + wk);
        ws[(wk + 0) * 128 + wm] = wv.x;
        ws[(wk + 1) * 128 + wm] = wv.y;
        ws[(wk + 2) * 128 + wm] = wv.z;
        ws[(wk + 3) * 128 + wm] = wv.w;
        float4 xv = *(const float4*)(Xb + (size_t)(k0 + xk) * N + n0 + xn4);
        *(float4*)&xs[xk * 128 + xn4] = xv;
        __syncthreads();
#pragma unroll
        for (int kk = 0; kk < 8; kk++) {
            float4 a0 = *(float4*)&ws[kk * 128 + ty * 8];
            float4 a1 = *(float4*)&ws[kk * 128 + ty * 8 + 4];
            float4 b0 = *(float4*)&xs[kk * 128 + tx * 8];
            float4 b1 = *(float4*)&xs[kk * 128 + tx * 8 + 4];
            float a[8] = {a0.x, a0.y, a0.z, a0.w, a1.x, a1.y, a1.z, a1.w};
            float bb[8] = {b0.x, b0.y, b0.z, b0.w, b1.x, b1.y, b1.z, b1.w};
#pragma unroll
            for (int i = 0; i < 8; i++)
#pragma unroll
                for (int j = 0; j < 8; j++) acc[i][j] += a[i] * bb[j];
        }
        __syncthreads();
    }

#pragma unroll
    for (int i = 0; i < 8; i++) {
        int m = m0 + ty * 8 + i;
        float bv = bias[m];
        size_t off = ((size_t)b * M + m) * N + n0 + tx * 8;
        float4 o0, o1;
        o0.x = acc[i][0] + bv; o0.y = acc[i][1] + bv; o0.z = acc[i][2] + bv; o0.w = acc[i][3] + bv;
        o1.x = acc[i][4] + bv; o1.y = acc[i][5] + bv; o1.z = acc[i][6] + bv; o1.w = acc[i][7] + bv;
        if (res) {
            float4 r0 = *(const float4*)(res + off);
            float4 r1 = *(const float4*)(res + off + 4);
            o0.x += r0.x; o0.y += r0.y; o0.z += r0.z; o0.w += r0.w;
            o1.x += r1.x; o1.y += r1.y; o1.z += r1.z; o1.w += r1.w;
        }
        *(float4*)(C + off) = o0;
        *(float4*)(C + off + 4) = o1;
    }
}

// ============================================================
// ckv GEMM: g_ckv[b][o][l] = sum_c context[b][l][c]*ckv_w[o][c] + ckv_b[o]
// block = (o-tile of 64, b). 64o x 80l tile (l padded), K-chunks of 32.
// ============================================================
__global__ void ckv_kernel(const float* __restrict__ ctx, const float* __restrict__ W,
                           const float* __restrict__ bias) {
    __shared__ float ws2[32 * 65];
    __shared__ float cs[32 * 81];
    int ot = blockIdx.x, b = blockIdx.y;
    int tid = threadIdx.x;
    int tx = tid & 15, tg = tid >> 4;
    int cc = tid & 31, rr = tid >> 5;  // cc: 0..31, rr: 0..7
    int ob = tg * 4, lb = tx * 5;

    float acc[4][5];
#pragma unroll
    for (int i = 0; i < 4; i++)
#pragma unroll
        for (int j = 0; j < 5; j++) acc[i][j] = 0.f;

    for (int c0 = 0; c0 < CTXD; c0 += 32) {
#pragma unroll
        for (int p = 0; p < 8; p++) {
            int o = p * 8 + rr;
            ws2[cc * 65 + o] = W[(size_t)(ot * 64 + o) * CTXD + c0 + cc];
        }
#pragma unroll
        for (int p = 0; p < 10; p++) {
            int l = p * 8 + rr;
            float v = (l < LCTX) ? ctx[((size_t)b * LCTX + l) * CTXD + c0 + cc] : 0.f;
            cs[cc * 81 + l] = v;
        }
        __syncthreads();
#pragma unroll
        for (int kk = 0; kk < 32; kk++) {
            float wv[4], cv[5];
#pragma unroll
            for (int i = 0; i < 4; i++) wv[i] = ws2[kk * 65 + ob + i];
#pragma unroll
            for (int j = 0; j < 5; j++) cv[j] = cs[kk * 81 + lb + j];
#pragma unroll
            for (int i = 0; i < 4; i++)
#pragma unroll
                for (int j = 0; j < 5; j++) acc[i][j] += wv[i] * cv[j];
        }
        __syncthreads();
    }

#pragma unroll
    for (int i = 0; i < 4; i++) {
        int o = ot * 64 + ob + i;
        float bv = bias[o];
#pragma unroll
        for (int j = 0; j < 5; j++) {
            int l = lb + j;
            if (l < LCTX)
                g_ckv[((size_t)b * 1024 + o) * LCTX + l] = acc[i][j] + bv;
        }
    }
}

// ============================================================
// Flash attention: block = (s-tile of 64, head, batch). 256 threads.
// KV = concat(ctx 77, image 1024) gathered in the loader.
// smem: qs[64][64], ks[64][64], vs[64][65] (t-major), ps[64][65]
// ============================================================
__global__ void flash_kernel() {
    extern __shared__ float sm[];
    float* qs = sm;                  // 4096
    float* ks = qs + 64 * 64;        // 4096
    float* vs = ks + 64 * 64;        // 64*65
    float* ps = vs + 64 * 65;        // 64*65

    int s0 = blockIdx.x * 64;
    int n = blockIdx.y, b = blockIdx.z;
    int tid = threadIdx.x;
    int tx = tid & 15, ty = tid >> 4;
    int lt = tid & 63, ld4 = tid >> 6;

    const float* qbase = g_qkv + ((size_t)b * 1536 + n * 64) * 1024 + s0;
    const float* kck = g_ckv + ((size_t)b * 1024 + n * 64) * LCTX;
    const float* vck = g_ckv + ((size_t)b * 1024 + 512 + n * 64) * LCTX;
    const float* kim = g_qkv + ((size_t)b * 1536 + 512 + n * 64) * 1024;
    const float* vim = g_qkv + ((size_t)b * 1536 + 1024 + n * 64) * 1024;

#pragma unroll
    for (int p = 0; p < 16; p++) {
        int d = p * 4 + ld4;
        qs[d * 64 + lt] = qbase[(size_t)d * 1024 + lt];
    }

    float m_i[4], l_i[4], acc_o[4][4];
#pragma unroll
    for (int i = 0; i < 4; i++) {
        m_i[i] = -1e30f; l_i[i] = 0.f;
#pragma unroll
        for (int j = 0; j < 4; j++) acc_o[i][j] = 0.f;
    }

    for (int c = 0; c < NCHUNK; c++) {
        int t0 = c * 64;
        // load K chunk [d][t] and V chunk transposed [t][d]
#pragma unroll
        for (int p = 0; p < 16; p++) {
            int d = p * 4 + ld4;
            int t = t0 + lt;
            float kv, vv;
            if (t < LCTX) {
                kv = kck[d * LCTX + t];
                vv = vck[d * LCTX + t];
            } else if (t < TKV) {
                kv = kim[(size_t)d * 1024 + (t - LCTX)];
                vv = vim[(size_t)d * 1024 + (t - LCTX)];
            } else {
                kv = 0.f; vv = 0.f;
            }
            ks[d * 64 + lt] = kv;
            vs[lt * 65 + d] = vv;
        }
        __syncthreads();

        // S = (Q^T K) / 8
        float s_acc[4][4];
#pragma unroll
        for (int i = 0; i < 4; i++)
#pragma unroll
            for (int j = 0; j < 4; j++) s_acc[i][j] = 0.f;
        for (int d = 0; d < 64; d++) {
            float4 a = *(float4*)&qs[d * 64 + ty * 4];
            float4 bb = *(float4*)&ks[d * 64 + tx * 4];
            float av[4] = {a.x, a.y, a.z, a.w};
            float bv[4] = {bb.x, bb.y, bb.z, bb.w};
#pragma unroll
            for (int i = 0; i < 4; i++)
#pragma unroll
                for (int j = 0; j < 4; j++) s_acc[i][j] += av[i] * bv[j];
        }
#pragma unroll
        for (int i = 0; i < 4; i++)
#pragma unroll
            for (int j = 0; j < 4; j++) {
                float sv = s_acc[i][j] * 0.125f;
                if (t0 + tx * 4 + j >= TKV) sv = -1e30f;
                s_acc[i][j] = sv;
            }

        // online softmax per row (row spread across 16 lanes)
#pragma unroll
        for (int i = 0; i < 4; i++) {
            float mx = fmaxf(fmaxf(s_acc[i][0], s_acc[i][1]), fmaxf(s_acc[i][2], s_acc[i][3]));
#pragma unroll
            for (int off = 8; off > 0; off >>= 1)
                mx = fmaxf(mx, __shfl_xor_sync(0xffffffffu, mx, off, 16));
            float mn = fmaxf(m_i[i], mx);
            float sc = __expf(m_i[i] - mn);
            m_i[i] = mn;
            float ls = 0.f;
#pragma unroll
            for (int j = 0; j < 4; j++) {
                float pv = __expf(s_acc[i][j] - mn);
                s_acc[i][j] = pv;
                ls += pv;
            }
#pragma unroll
            for (int off = 8; off > 0; off >>= 1)
                ls += __shfl_xor_sync(0xffffffffu, ls, off, 16);
            l_i[i] = l_i[i] * sc + ls;
#pragma unroll
            for (int j = 0; j < 4; j++) acc_o[i][j] *= sc;
#pragma unroll
            for (int j = 0; j < 4; j++) ps[(ty * 4 + i) * 65 + tx * 4 + j] = s_acc[i][j];
        }
        __syncthreads();

        // O[ss][d] += sum_tt P[ss][tt] * V[tt][d]
        for (int tt = 0; tt < 64; tt++) {
            float a0 = ps[(ty * 4 + 0) * 65 + tt];
            float a1 = ps[(ty * 4 + 1) * 65 + tt];
            float a2 = ps[(ty * 4 + 2) * 65 + tt];
            float a3 = ps[(ty * 4 + 3) * 65 + tt];
            float b0 = vs[tt * 65 + tx * 4 + 0];
            float b1 = vs[tt * 65 + tx * 4 + 1];
            float b2 = vs[tt * 65 + tx * 4 + 2];
            float b3 = vs[tt * 65 + tx * 4 + 3];
            acc_o[0][0] += a0 * b0; acc_o[0][1] += a0 * b1; acc_o[0][2] += a0 * b2; acc_o[0][3] += a0 * b3;
            acc_o[1][0] += a1 * b0; acc_o[1][1] += a1 * b1; acc_o[1][2] += a1 * b2; acc_o[1][3] += a1 * b3;
            acc_o[2][0] += a2 * b0; acc_o[2][1] += a2 * b1; acc_o[2][2] += a2 * b2; acc_o[2][3] += a2 * b3;
            acc_o[3][0] += a3 * b0; acc_o[3][1] += a3 * b1; acc_o[3][2] += a3 * b2; acc_o[3][3] += a3 * b3;
        }
        __syncthreads();
    }

    // normalize + stage through smem for coalesced output
#pragma unroll
    for (int i = 0; i < 4; i++) {
        float inv = 1.f / l_i[i];
#pragma unroll
        for (int j = 0; j < 4; j++)
            ps[(ty * 4 + i) * 65 + tx * 4 + j] = acc_o[i][j] * inv;
    }
    __syncthreads();

    float* outp = g_attn + ((size_t)b * 512 + n * 64) * 1024 + s0;
#pragma unroll
    for (int p = 0; p < 16; p++) {
        int d = p * 4 + ld4;
        outp[(size_t)d * 1024 + lt] = ps[lt * 65 + d];
    }
}

// ============================================================
extern "C" void kernel_launch(void* const* d_in, const int* in_sizes, int n_in,
                              void* d_out, int out_size) {
    const float* x       = (const float*)d_in[0];
    const float* context = (const float*)d_in[1];
    const float* gamma   = (const float*)d_in[2];
    const float* beta    = (const float*)d_in[3];
    const float* qkv_w   = (const float*)d_in[4];
    const float* qkv_b   = (const float*)d_in[5];
    const float* ckv_w   = (const float*)d_in[6];
    const float* ckv_b   = (const float*)d_in[7];
    const float* proj_w  = (const float*)d_in[8];
    const float* proj_b  = (const float*)d_in[9];
    float* out = (float*)d_out;

    float *xn_p, *qkv_p, *attn_p;
    cudaGetSymbolAddress((void**)&xn_p, g_xn);
    cudaGetSymbolAddress((void**)&qkv_p, g_qkv);
    cudaGetSymbolAddress((void**)&attn_p, g_attn);

    // 1. GroupNorm
    gn_kernel<<<BATCH * 32, 256>>>(x, gamma, beta, xn_p);

    // 2. QKV projection: M=1536, N=1024, K=512, batched 8
    gemm128<<<dim3(8, 12, BATCH), 256>>>(qkv_w, qkv_b, xn_p, nullptr, qkv_p, 1536, 1024, 512);

    // 3. Context KV projection
    ckv_kernel<<<dim3(16, BATCH), 256>>>(context, ckv_w, ckv_b);

    // 4. Flash attention
    int smem = (64 * 64 * 2 + 64 * 65 * 2) * (int)sizeof(float);  // 66048 B
    cudaFuncSetAttribute(flash_kernel, cudaFuncAttributeMaxDynamicSharedMemorySize, smem);
    flash_kernel<<<dim3(16, HEADS, BATCH), 256, smem>>>();

    // 5. Output projection + bias + residual
    gemm128<<<dim3(8, 4, BATCH), 256>>>(proj_w, proj_b, attn_p, x, out, 512, 1024, 512);
}